// round 9
// baseline (speedup 1.0000x reference)
#include <cuda_runtime.h>

#define BB 8
#define LL 512
#define KK 512
#define MM 64
#define NN 64
#define PDIM 64
#define DD 64

// scratch (device globals; no allocations)
__device__ float g_sum4[BB * 4 * LL];             // 64 KB per-(b,ktile) partial row sums
__device__ float g_vkc [BB * KK * NN];            // 1 MB
__device__ float g_tmp4[BB * 4 * LL * NN];        // 4 MB split-K partial (unnormalized) tmp

// ============ K1: vkc[b,k,n] = sum_p vk[b,k,p,n] * vexp[b,k,p] ============
__global__ void __launch_bounds__(256) kv_kernel(
    const float* __restrict__ vk, const float* __restrict__ vexp) {
    __shared__ float sve[256];
    __shared__ __align__(16) float4 red[256];
    int t = threadIdx.x;
    int bk0 = blockIdx.x * 4;

    sve[t] = vexp[(size_t)bk0 * PDIM + t];
    __syncthreads();

    int slab = t >> 6;
    int tt = t & 63;
    int n4 = tt & 15;
    int pg = tt >> 4;
    const float4* vk4 = (const float4*)(vk + (size_t)(bk0 + slab) * PDIM * NN);
    const float* ve = &sve[slab * 64];
    float4 acc = make_float4(0.f, 0.f, 0.f, 0.f);
#pragma unroll
    for (int i = 0; i < 16; i++) {
        int p = pg * 16 + i;
        float4 a = vk4[p * 16 + n4];
        float e = ve[p];
        acc.x += a.x * e; acc.y += a.y * e; acc.z += a.z * e; acc.w += a.w * e;
    }
    red[t] = acc;
    __syncthreads();
    if (tt < 16) {
        float4 r0 = red[slab * 64 + n4];
        float4 r1 = red[slab * 64 + 16 + n4];
        float4 r2 = red[slab * 64 + 32 + n4];
        float4 r3 = red[slab * 64 + 48 + n4];
        float4 o = make_float4(r0.x + r1.x + r2.x + r3.x, r0.y + r1.y + r2.y + r3.y,
                               r0.z + r1.z + r2.z + r3.z, r0.w + r1.w + r2.w + r3.w);
        *(float4*)&g_vkc[(size_t)(bk0 + slab) * NN + n4 * 4] = o;
    }
}

// ============ K2: fused scores(128x128) + exp + (E @ vkc), split-K ============
// smem 103KB (Es overlaps dead qT) -> 2 CTAs/SM:
//   kb[128][68] (k tile -> vkc chunk) | region2: qT[64][132] then Es[128][132] | ssum[128]
#define KBS 68
#define QTS 132
#define ESS 132
#define OFF_R2  (128 * KBS)
#define OFF_SS  (OFF_R2 + 128 * ESS)
#define SMEM_KS (OFF_SS + 128)

__global__ void __launch_bounds__(256, 2) ks_kernel(
    const float* __restrict__ q, const float* __restrict__ k,
    const float* __restrict__ scale_p) {
    extern __shared__ float s[];
    float* kb   = s;               // [128][KBS]
    float* qT   = s + OFF_R2;      // [64][QTS]   qT[d][l]   (phase 1)
    float* Es   = s + OFF_R2;      // [128][ESS]  Es[k][l]   (phase 2, overlaps qT)
    float* ssum = s + OFF_SS;      // [128]
    int t = threadIdx.x;
    int bid = blockIdx.x;
    int b  = bid >> 4;
    int r  = bid & 15;
    int l0 = (r >> 2) * 128;
    int kt = r & 3;
    int k0 = kt * 128;

    // load k tile [128][64]
#pragma unroll
    for (int j = 0; j < 8; j++) {
        int v = t + j * 256;
        int row = v >> 4, c4 = v & 15;
        float4 x = *(const float4*)&k[((size_t)(b * KK + k0 + row)) * DD + c4 * 4];
        *(float4*)&kb[row * KBS + c4 * 4] = x;
    }
    // transpose q tile [128 l][64 d] -> qT[d][l]
#pragma unroll
    for (int j = 0; j < 8; j++) {
        int v = t + j * 256;
        int l = v >> 4, d4 = v & 15;
        float4 x = *(const float4*)&q[((size_t)(b * LL + l0 + l)) * DD + d4 * 4];
        qT[(d4 * 4 + 0) * QTS + l] = x.x;
        qT[(d4 * 4 + 1) * QTS + l] = x.y;
        qT[(d4 * 4 + 2) * QTS + l] = x.z;
        qT[(d4 * 4 + 3) * QTS + l] = x.w;
    }
    if (t < 128) ssum[t] = 0.f;
    __syncthreads();

    // ---- GEMM1: scores 8k x 8l per thread ----
    int tkg = t >> 4;      // 16 k-groups of 8
    int tlg = t & 15;      // 16 l-groups of 8
    float acc[8][8];
#pragma unroll
    for (int a = 0; a < 8; a++)
#pragma unroll
        for (int c = 0; c < 8; c++) acc[a][c] = 0.f;

    for (int d0 = 0; d0 < DD; d0 += 4) {
        float4 kv[8];
#pragma unroll
        for (int ki = 0; ki < 8; ki++)
            kv[ki] = *(float4*)&kb[(tkg * 8 + ki) * KBS + d0];
#pragma unroll
        for (int dd = 0; dd < 4; dd++) {
            float4 qa = *(float4*)&qT[(d0 + dd) * QTS + tlg * 8];
            float4 qb = *(float4*)&qT[(d0 + dd) * QTS + tlg * 8 + 4];
            float ql[8] = {qa.x, qa.y, qa.z, qa.w, qb.x, qb.y, qb.z, qb.w};
#pragma unroll
            for (int ki = 0; ki < 8; ki++) {
                float kd = ((float*)&kv[ki])[dd];
#pragma unroll
                for (int lj = 0; lj < 8; lj++) acc[ki][lj] += kd * ql[lj];
            }
        }
    }
    __syncthreads();   // all GEMM1 reads of kb/qT done; qT region becomes Es

    // ---- exp -> Es, row-sum partials; vkc chunk -> kb ----
    float scale = *scale_p;
    float sacc[8];
#pragma unroll
    for (int j = 0; j < 8; j++) sacc[j] = 0.f;
#pragma unroll
    for (int ki = 0; ki < 8; ki++) {
        float4 e0, e1;
        e0.x = __expf(acc[ki][0] * scale);
        e0.y = __expf(acc[ki][1] * scale);
        e0.z = __expf(acc[ki][2] * scale);
        e0.w = __expf(acc[ki][3] * scale);
        e1.x = __expf(acc[ki][4] * scale);
        e1.y = __expf(acc[ki][5] * scale);
        e1.z = __expf(acc[ki][6] * scale);
        e1.w = __expf(acc[ki][7] * scale);
        sacc[0] += e0.x; sacc[1] += e0.y; sacc[2] += e0.z; sacc[3] += e0.w;
        sacc[4] += e1.x; sacc[5] += e1.y; sacc[6] += e1.z; sacc[7] += e1.w;
        *(float4*)&Es[(tkg * 8 + ki) * ESS + tlg * 8]     = e0;
        *(float4*)&Es[(tkg * 8 + ki) * ESS + tlg * 8 + 4] = e1;
    }
#pragma unroll
    for (int j = 0; j < 8; j++) atomicAdd(&ssum[tlg * 8 + j], sacc[j]);
    // vkc chunk [128][64] into kb
#pragma unroll
    for (int j = 0; j < 8; j++) {
        int v = t + j * 256;
        int row = v >> 4, c4 = v & 15;
        float4 x = *(const float4*)&g_vkc[((size_t)(b * KK + k0 + row)) * NN + c4 * 4];
        *(float4*)&kb[row * KBS + c4 * 4] = x;
    }
    __syncthreads();
    if (t < 128) g_sum4[((size_t)(b * 4 + kt)) * LL + l0 + t] = ssum[t];

    // ---- GEMM2: tmp_partial[l][n] = sum_k Es[k][l]*vkc[k][n]; 8l x 4n ----
    int tl = t & 15;       // l-group of 8
    int tn = t >> 4;       // n-group of 4
    float acc2[8][4];
#pragma unroll
    for (int a = 0; a < 8; a++)
#pragma unroll
        for (int c = 0; c < 4; c++) acc2[a][c] = 0.f;
#pragma unroll 2
    for (int kk = 0; kk < 128; kk++) {
        float4 ea = *(float4*)&Es[kk * ESS + tl * 8];
        float4 eb = *(float4*)&Es[kk * ESS + tl * 8 + 4];
        float4 v4 = *(float4*)&kb[kk * KBS + tn * 4];
        float ee[8] = {ea.x, ea.y, ea.z, ea.w, eb.x, eb.y, eb.z, eb.w};
        float vv[4] = {v4.x, v4.y, v4.z, v4.w};
#pragma unroll
        for (int li = 0; li < 8; li++)
#pragma unroll
            for (int nj = 0; nj < 4; nj++)
                acc2[li][nj] += ee[li] * vv[nj];
    }
#pragma unroll
    for (int li = 0; li < 8; li++) {
        int l = l0 + tl * 8 + li;
        float4 o = {acc2[li][0], acc2[li][1], acc2[li][2], acc2[li][3]};
        *(float4*)&g_tmp4[(((size_t)(b * 4 + kt)) * LL + l) * NN + tn * 4] = o;
    }
}

// ============ K3: attn = vq @ tmp (combined+normalized), residual + LN ============
// 2 rows per block: 8 front-batched LDG.128/thread, shared syncs.
__global__ void __launch_bounds__(256) k3_kernel(
    const float* __restrict__ q, const float* __restrict__ vq,
    const float* __restrict__ gamma, const float* __restrict__ beta,
    float* __restrict__ out) {
    int bl0 = blockIdx.x * 2;        // rows bl0, bl0+1
    int b = bl0 >> 9;
    __shared__ __align__(16) float stmp[2][64];
    __shared__ float sq[2][64];
    __shared__ float so[2][64];
    __shared__ float rs[2][8], rq[2][8];
    int t = threadIdx.x;
    if (t < 128) {
        int rr = t >> 6, tt = t & 63;
        int l = (bl0 & 511) + rr;
        float ssum = 0.f, v = 0.f;
#pragma unroll
        for (int i = 0; i < 4; i++) {
            ssum += g_sum4[((size_t)(b * 4 + i)) * LL + l];
            v    += g_tmp4[(((size_t)(b * 4 + i)) * LL + l) * NN + tt];
        }
        stmp[rr][tt] = v / ssum;
        sq[rr][tt]   = q[(size_t)(bl0 + rr) * DD + tt];
    }
    __syncthreads();

    int n4 = t & 15;
    const float4* vq0 = (const float4*)(vq + (size_t)bl0 * MM * NN);
    const float4* vq1 = vq0 + 1024;
    float4 va[4], vb[4];
#pragma unroll
    for (int i = 0; i < 4; i++) va[i] = vq0[t + i * 256];
#pragma unroll
    for (int i = 0; i < 4; i++) vb[i] = vq1[t + i * 256];

    float4 tm0 = ((float4*)stmp[0])[n4];
    float4 tm1 = ((float4*)stmp[1])[n4];
    float p0[4], p1[4];
#pragma unroll
    for (int i = 0; i < 4; i++) {
        p0[i] = va[i].x * tm0.x + va[i].y * tm0.y + va[i].z * tm0.z + va[i].w * tm0.w;
        p1[i] = vb[i].x * tm1.x + vb[i].y * tm1.y + vb[i].z * tm1.z + vb[i].w * tm1.w;
    }
#pragma unroll
    for (int o = 8; o; o >>= 1)
#pragma unroll
        for (int i = 0; i < 4; i++) {
            p0[i] += __shfl_down_sync(0xFFFFFFFFu, p0[i], o, 16);
            p1[i] += __shfl_down_sync(0xFFFFFFFFu, p1[i], o, 16);
        }
    if ((t & 15) == 0) {
        int g = t >> 4;
#pragma unroll
        for (int i = 0; i < 4; i++) {
            so[0][g + 16 * i] = p0[i];
            so[1][g + 16 * i] = p1[i];
        }
    }
    __syncthreads();

    int m = t & 63;
    int lane = t & 31, w = t >> 5;
    float x0 = sq[0][m] + so[0][m];          // residual (M == D)
    float x1 = sq[1][m] + so[1][m];
    float a0 = x0, q0 = x0 * x0, a1 = x1, q1 = x1 * x1;
#pragma unroll
    for (int o = 16; o; o >>= 1) {
        a0 += __shfl_xor_sync(0xFFFFFFFFu, a0, o);
        q0 += __shfl_xor_sync(0xFFFFFFFFu, q0, o);
        a1 += __shfl_xor_sync(0xFFFFFFFFu, a1, o);
        q1 += __shfl_xor_sync(0xFFFFFFFFu, q1, o);
    }
    if (lane == 0) { rs[0][w] = a0; rq[0][w] = q0; rs[1][w] = a1; rq[1][w] = q1; }
    __syncthreads();
    float sa0 = 0.f, sq0 = 0.f, sa1 = 0.f, sq1 = 0.f;
#pragma unroll
    for (int i = 0; i < 8; i++) {
        sa0 += rs[0][i]; sq0 += rq[0][i];
        sa1 += rs[1][i]; sq1 += rq[1][i];
    }
    if (t < 64) {
        float gm = gamma[m], bt = beta[m];
        float mu0   = sa0 * (1.f / 256.f);   // each m replicated 4x -> exact mean
        float var0  = sq0 * (1.f / 256.f) - mu0 * mu0;
        float mu1   = sa1 * (1.f / 256.f);
        float var1  = sq1 * (1.f / 256.f) - mu1 * mu1;
        out[(size_t)bl0 * MM + m]       = (x0 - mu0) * rsqrtf(var0 + 1e-3f) * gm + bt;
        out[(size_t)(bl0 + 1) * MM + m] = (x1 - mu1) * rsqrtf(var1 + 1e-3f) * gm + bt;
    }
}

extern "C" void kernel_launch(void* const* d_in, const int* in_sizes, int n_in,
                              void* d_out, int out_size) {
    const float* q     = (const float*)d_in[0];
    const float* k     = (const float*)d_in[1];
    const float* vq    = (const float*)d_in[2];
    const float* vk    = (const float*)d_in[3];
    const float* vexp  = (const float*)d_in[4];
    const float* scale = (const float*)d_in[5];
    const float* gamma = (const float*)d_in[6];
    const float* beta  = (const float*)d_in[7];
    float* out = (float*)d_out;

    kv_kernel<<<BB * KK / 4, 256>>>(vk, vexp);

    int smemS = SMEM_KS * (int)sizeof(float);
    cudaFuncSetAttribute(ks_kernel, cudaFuncAttributeMaxDynamicSharedMemorySize, smemS);
    ks_kernel<<<128, 256, smemS>>>(q, k, scale);

    k3_kernel<<<BB * LL / 2, 256>>>(q, vq, gamma, beta, out);
}